// round 11
// baseline (speedup 1.0000x reference)
#include <cuda_runtime.h>

// NNSystem_mech RHS, one warp, one launch. FINAL structure = R7, re-benched.
// Evidence trail:
//   R4 monolithic warp:        kernel 5.95us
//   R5 chain cuts:             kernel 5.06us
//   R7 half-warp branch split: kernel 4.54us  <- best
//   R8 2-unit fold:            kernel 4.80us  (regressed: extra MUFU+FMA on lane)
//   R9 branchless:             kernel 5.12us  (regressed: at 1 warp, if-arms
//                               with no else cost ~nothing; FSEL/clamp added issues)
// redux.sync.add.f32 rejected by ptxas on sm_103 (R8 attempt).
// Harness dur carries 0.3-2.3us uncorrelated replay overhead; kernel dur is
// the real objective and this source holds the measured minimum.
//
// Structure: lanes 0-15 compute the ACTH branch, lanes 16-31 cortisol.
// Butterfly offsets 8/4/2/1 never cross the 16-lane boundary, so both
// branches reduce simultaneously in the same 8 SHFL instructions.

__device__ __forceinline__ float sp(float x) {
    // direct softplus: all pre-activations here are O(1); no overflow risk.
    return __logf(1.0f + __expf(x));
}

__global__ void __launch_bounds__(32, 1) nnsys_kernel(
    const float* __restrict__ y,
    const float* __restrict__ aiw, const float* __restrict__ aib,
    const float* __restrict__ apw1, const float* __restrict__ apb1,
    const float* __restrict__ apw2, const float* __restrict__ apb2,
    const float* __restrict__ anw1, const float* __restrict__ anb1,
    const float* __restrict__ anw2, const float* __restrict__ anb2,
    const float* __restrict__ arw,  const float* __restrict__ arb,
    const float* __restrict__ ciw,  const float* __restrict__ cib,
    const float* __restrict__ cpw1, const float* __restrict__ cpb1,
    const float* __restrict__ cpw2, const float* __restrict__ cpb2,
    const float* __restrict__ cnw1, const float* __restrict__ cnb1,
    const float* __restrict__ cnw2, const float* __restrict__ cnb2,
    const float* __restrict__ crw,  const float* __restrict__ crb,
    const float* __restrict__ K_i,  const float* __restrict__ n_hill,
    float* __restrict__ out)
{
    const int lane  = threadIdx.x;
    const int j     = lane & 15;         // index within half
    const bool cort = lane >= 16;        // which branch this half computes

    // ---- per-half operand selection (SEL pairs, off the critical path) ----
    const float* iw  = cort ? ciw  : aiw;
    const float* ib  = cort ? cib  : aib;
    const float* pw1 = cort ? cpw1 : apw1;
    const float* pb1 = cort ? cpb1 : apb1;
    const float* pw2 = cort ? cpw2 : apw2;
    const float* nw1 = cort ? cnw1 : anw1;
    const float* nb1 = cort ? cnb1 : anb1;
    const float* nw2 = cort ? cnw2 : anw2;

    // ---- front-batched loads ----
    const float2 yv = *reinterpret_cast<const float2*>(y);   // y0, y1
    const float yin = cort ? yv.y : yv.x;

    const float pb2 = cort ? cpb2[0] : apb2[0];
    const float nb2 = cort ? cnb2[0] : anb2[0];
    const float rw0 = cort ? crw[0]  : arw[0];
    const float rw1 = cort ? crw[1]  : arw[1];
    const float rb  = cort ? crb[0]  : arb[0];
    const float Kv  = K_i[0], nH = n_hill[0];

    // ---- initial 1->2 linear + softplus (per half; independent chains) ----
    const float h0 = sp(fmaf(iw[0], yin, ib[0]));
    const float h1 = sp(fmaf(iw[1], yin, ib[1]));

    // ---- tiny MLPs: lane j<10 of each half owns hidden unit j ----
    float pp = 0.0f, nn = 0.0f;
    if (j < 10) {
        pp = pw2[j] * sp(fmaf(pw1[j], h0, pb1[j]));
        nn = nw2[j] * sp(fmaf(nw1[j], h1, nb1[j]));
    }

    // ---- Hill term (only lane 0 consumes it; computed everywhere so its
    //      MUFU chain overlaps the butterfly). K=1.5>0, y1 in (0,1). ----
    const float Kn   = __powf(Kv, nH);
    const float hill = __fdividef(Kn, Kn + __powf(yv.y, nH));

    // ---- 4-step butterfly within each 16-lane half (offsets < 16) ----
    #pragma unroll
    for (int ofs = 8; ofs > 0; ofs >>= 1) {
        pp += __shfl_xor_sync(0xFFFFFFFFu, pp, ofs);
        nn += __shfl_xor_sync(0xFFFFFFFFu, nn, ofs);
    }

    // ---- epilogue: lane 0 (ACTH) and lane 16 (cortisol) concurrently ----
    if (j == 0) {
        const float gate   = cort ? yv.x : hill;     // y0 * c_pos vs hill * a_pos
        const float pos_in = gate * (pp + pb2);
        const float neg_in = nn + nb2;
        out[(int)cort] = fmaf(rw0, sp(pos_in), fmaf(rw1, sp(neg_in), rb));
    }
}

extern "C" void kernel_launch(void* const* d_in, const int* in_sizes, int n_in,
                              void* d_out, int out_size) {
    // metadata order mirrors reference() signature:
    //  0:t 1:y 2:aiw 3:aib 4:apw1 5:apb1 6:apw2 7:apb2
    //  8:anw1 9:anb1 10:anw2 11:anb2 12:arw 13:arb
    // 14:ciw 15:cib 16:cpw1 17:cpb1 18:cpw2 19:cpb2
    // 20:cnw1 21:cnb1 22:cnw2 23:cnb2 24:crw 25:crb 26:K_i 27:n_hill
    nnsys_kernel<<<1, 32>>>(
        (const float*)d_in[1],
        (const float*)d_in[2],  (const float*)d_in[3],
        (const float*)d_in[4],  (const float*)d_in[5],
        (const float*)d_in[6],  (const float*)d_in[7],
        (const float*)d_in[8],  (const float*)d_in[9],
        (const float*)d_in[10], (const float*)d_in[11],
        (const float*)d_in[12], (const float*)d_in[13],
        (const float*)d_in[14], (const float*)d_in[15],
        (const float*)d_in[16], (const float*)d_in[17],
        (const float*)d_in[18], (const float*)d_in[19],
        (const float*)d_in[20], (const float*)d_in[21],
        (const float*)d_in[22], (const float*)d_in[23],
        (const float*)d_in[24], (const float*)d_in[25],
        (const float*)d_in[26], (const float*)d_in[27],
        (float*)d_out);
}

// round 12
// speedup vs baseline: 1.4897x; 1.4897x over previous
#include <cuda_runtime.h>

// NNSystem_mech RHS, one warp, one launch. LOCKED structure (= R7/R10 source).
//
// Measurement model (7 bench samples):
//   - kernel dur: 4.54-4.80us for THIS source (identical bytes, two runs) ->
//     +-0.25us DVFS/ramp noise; structural variants R8 (4.80) and R9 (5.12)
//     are within/near that band. Fixed launch overhead (~5000cyc T_ovh at
//     ~1.1GHz ~= 4.5us) dominates; the ~400cyc compute chain is <10% of dur.
//   - harness dur: kernel + 1.4-2.4us uncorrelated replay overhead.
//     Best-so-far 6.21us came from a favorable draw on a SLOWER (5.06us)
//     kernel. Scored metric is draw-dominated at this scale.
// Conclusion: controllable floor reached; resubmit the proven minimum.
//   - redux.sync.add.f32: rejected by ptxas on sm_103 (R8).
//   - 2-unit/lane fold (R8) and full predication (R9): no improvement.
//
// Structure: lanes 0-15 compute the ACTH branch, lanes 16-31 cortisol.
// Butterfly offsets 8/4/2/1 never cross the 16-lane boundary, so both
// branches reduce simultaneously in the same 8 SHFL instructions.

__device__ __forceinline__ float sp(float x) {
    // direct softplus: all pre-activations here are O(1); no overflow risk.
    return __logf(1.0f + __expf(x));
}

__global__ void __launch_bounds__(32, 1) nnsys_kernel(
    const float* __restrict__ y,
    const float* __restrict__ aiw, const float* __restrict__ aib,
    const float* __restrict__ apw1, const float* __restrict__ apb1,
    const float* __restrict__ apw2, const float* __restrict__ apb2,
    const float* __restrict__ anw1, const float* __restrict__ anb1,
    const float* __restrict__ anw2, const float* __restrict__ anb2,
    const float* __restrict__ arw,  const float* __restrict__ arb,
    const float* __restrict__ ciw,  const float* __restrict__ cib,
    const float* __restrict__ cpw1, const float* __restrict__ cpb1,
    const float* __restrict__ cpw2, const float* __restrict__ cpb2,
    const float* __restrict__ cnw1, const float* __restrict__ cnb1,
    const float* __restrict__ cnw2, const float* __restrict__ cnb2,
    const float* __restrict__ crw,  const float* __restrict__ crb,
    const float* __restrict__ K_i,  const float* __restrict__ n_hill,
    float* __restrict__ out)
{
    const int lane  = threadIdx.x;
    const int j     = lane & 15;         // index within half
    const bool cort = lane >= 16;        // which branch this half computes

    // ---- per-half operand selection (SEL pairs, off the critical path) ----
    const float* iw  = cort ? ciw  : aiw;
    const float* ib  = cort ? cib  : aib;
    const float* pw1 = cort ? cpw1 : apw1;
    const float* pb1 = cort ? cpb1 : apb1;
    const float* pw2 = cort ? cpw2 : apw2;
    const float* nw1 = cort ? cnw1 : anw1;
    const float* nb1 = cort ? cnb1 : anb1;
    const float* nw2 = cort ? cnw2 : anw2;

    // ---- front-batched loads ----
    const float2 yv = *reinterpret_cast<const float2*>(y);   // y0, y1
    const float yin = cort ? yv.y : yv.x;

    const float pb2 = cort ? cpb2[0] : apb2[0];
    const float nb2 = cort ? cnb2[0] : anb2[0];
    const float rw0 = cort ? crw[0]  : arw[0];
    const float rw1 = cort ? crw[1]  : arw[1];
    const float rb  = cort ? crb[0]  : arb[0];
    const float Kv  = K_i[0], nH = n_hill[0];

    // ---- initial 1->2 linear + softplus (per half; independent chains) ----
    const float h0 = sp(fmaf(iw[0], yin, ib[0]));
    const float h1 = sp(fmaf(iw[1], yin, ib[1]));

    // ---- tiny MLPs: lane j<10 of each half owns hidden unit j ----
    float pp = 0.0f, nn = 0.0f;
    if (j < 10) {
        pp = pw2[j] * sp(fmaf(pw1[j], h0, pb1[j]));
        nn = nw2[j] * sp(fmaf(nw1[j], h1, nb1[j]));
    }

    // ---- Hill term (only lane 0 consumes it; computed everywhere so its
    //      MUFU chain overlaps the butterfly). K=1.5>0, y1 in (0,1). ----
    const float Kn   = __powf(Kv, nH);
    const float hill = __fdividef(Kn, Kn + __powf(yv.y, nH));

    // ---- 4-step butterfly within each 16-lane half (offsets < 16) ----
    #pragma unroll
    for (int ofs = 8; ofs > 0; ofs >>= 1) {
        pp += __shfl_xor_sync(0xFFFFFFFFu, pp, ofs);
        nn += __shfl_xor_sync(0xFFFFFFFFu, nn, ofs);
    }

    // ---- epilogue: lane 0 (ACTH) and lane 16 (cortisol) concurrently ----
    if (j == 0) {
        const float gate   = cort ? yv.x : hill;     // y0 * c_pos vs hill * a_pos
        const float pos_in = gate * (pp + pb2);
        const float neg_in = nn + nb2;
        out[(int)cort] = fmaf(rw0, sp(pos_in), fmaf(rw1, sp(neg_in), rb));
    }
}

extern "C" void kernel_launch(void* const* d_in, const int* in_sizes, int n_in,
                              void* d_out, int out_size) {
    // metadata order mirrors reference() signature:
    //  0:t 1:y 2:aiw 3:aib 4:apw1 5:apb1 6:apw2 7:apb2
    //  8:anw1 9:anb1 10:anw2 11:anb2 12:arw 13:arb
    // 14:ciw 15:cib 16:cpw1 17:cpb1 18:cpw2 19:cpb2
    // 20:cnw1 21:cnb1 22:cnw2 23:cnb2 24:crw 25:crb 26:K_i 27:n_hill
    nnsys_kernel<<<1, 32>>>(
        (const float*)d_in[1],
        (const float*)d_in[2],  (const float*)d_in[3],
        (const float*)d_in[4],  (const float*)d_in[5],
        (const float*)d_in[6],  (const float*)d_in[7],
        (const float*)d_in[8],  (const float*)d_in[9],
        (const float*)d_in[10], (const float*)d_in[11],
        (const float*)d_in[12], (const float*)d_in[13],
        (const float*)d_in[14], (const float*)d_in[15],
        (const float*)d_in[16], (const float*)d_in[17],
        (const float*)d_in[18], (const float*)d_in[19],
        (const float*)d_in[20], (const float*)d_in[21],
        (const float*)d_in[22], (const float*)d_in[23],
        (const float*)d_in[24], (const float*)d_in[25],
        (const float*)d_in[26], (const float*)d_in[27],
        (float*)d_out);
}